// round 14
// baseline (speedup 1.0000x reference)
#include <cuda_runtime.h>
#include <math.h>
#include <stdint.h>

// Problem constants
#define B 4
#define NPTS 8192
#define KNN 20
#define OCH 64
#define EPS 1e-5
#define SLOPE 0.2f
#define INFF __int_as_float(0x7f800000)

// k_knn grid: 32 blocks x 256 threads per batch
#define KBLK 32
#define KTHR 256

// dynamic smem: [0,128K) staged points, then 8 per-warp lane queues depth 48
#define PTS_BYTES (NPTS * 16)
#define QDEPTH 48
#define WQ_BYTES (32 * QDEPTH * 8)                  // 12288 per warp
#define SMEM_TOTAL (PTS_BYTES + 8 * WQ_BYTES)       // 224 KB

// Device scratch (no allocations allowed)
__device__ int    g_idx[B * NPTS * KNN];
__device__ double g_bpart[B][KBLK][27];   // per-block moment partials (overwritten)

// ---------------------------------------------------------------------------
// Branchless stable insertion into sorted-ascending (d, j) list of 20.
// Upper-bound placement (strict <): ties land AFTER equal entries; candidates
// arrive in ascending j -> jax top_k boundary semantics. Idempotent for +INF.
// ---------------------------------------------------------------------------
__device__ __forceinline__ void insert_dj(float (&sd)[KNN], int (&sj)[KNN],
                                          float vd, int vj) {
    bool c[KNN];
#pragma unroll
    for (int k = 0; k < KNN; k++) c[k] = vd < sd[k];
#pragma unroll
    for (int k = KNN - 1; k >= 1; k--) {
        float td = c[k] ? vd : sd[k];
        int   tj = c[k] ? vj : sj[k];
        sd[k] = c[k - 1] ? sd[k - 1] : td;
        sj[k] = c[k - 1] ? sj[k - 1] : tj;
    }
    sd[0] = c[0] ? vd : sd[0];
    sj[0] = c[0] ? vj : sj[0];
}

// ---------------------------------------------------------------------------
// Kernel 1: flat exact KNN + per-block moment partials. Hot loop per
// 32-point group: PHASE 1 pure LDS+math (batched LDS.128), PHASE 2 fused
// predicated PTX (setp.lt + @p st + @p running-address add) -> 3 instr/pt,
// no per-point IMAD. cnt derived once per group from the running pointer.
// One uniform drain-check branch per group. Shifted distance d' = d - |q|^2
// (monotone per query; selected index SET unchanged).
// ---------------------------------------------------------------------------
__global__ void __launch_bounds__(KTHR) k_knn(const float* __restrict__ x) {
    extern __shared__ char sm[];
    float4* s_pts = (float4*)sm;
    __shared__ double sh[27];

    const int b = blockIdx.y;
    const float* xb = x + b * 3 * NPTS;

    for (int j = threadIdx.x; j < NPTS; j += KTHR) {
        float a0 = xb[j];
        float a1 = xb[NPTS + j];
        float a2 = xb[2 * NPTS + j];
        float sq = fmaf(a0, a0, fmaf(a1, a1, a2 * a2));
        s_pts[j] = make_float4(-2.0f * a0, -2.0f * a1, -2.0f * a2, sq);
    }
    __syncthreads();

    const int tid = threadIdx.x;
    const int i = blockIdx.x * KTHR + tid;
    const float4 ps = s_pts[i];
    const float qx = -0.5f * ps.x, qy = -0.5f * ps.y, qz = -0.5f * ps.z;

    uint32_t sbase;
    asm("{ .reg .u64 t; cvta.to.shared.u64 t, %1; cvt.u32.u64 %0, t; }"
        : "=r"(sbase) : "l"(sm));
    const uint32_t bufA = sbase + (uint32_t)PTS_BYTES +
                          (uint32_t)(tid >> 5) * (uint32_t)WQ_BYTES +
                          (uint32_t)(tid & 31) * 8u;
    const float2* bufP = (const float2*)(sm + PTS_BYTES +
                          (tid >> 5) * WQ_BYTES + (tid & 31) * 8);

    float sd[KNN];
    int   sj[KNN];
#pragma unroll
    for (int k = 0; k < KNN; k++) { sd[k] = INFF; sj[k] = 0; }
    float worst = INFF;
    uint32_t a = bufA;       // running queue pointer (entry stride 256 B)

#define DRAIN(cntv) do {                                               \
        for (int e = 0; __any_sync(0xffffffffu, e < (cntv)); e++) {    \
            float2 v = bufP[e * 32];                                   \
            float vd = (e < (cntv)) ? v.x : INFF;                      \
            insert_dj(sd, sj, vd, __float_as_int(v.y));                \
        }                                                              \
        worst = sd[KNN - 1];                                           \
        a = bufA;                                                      \
    } while (0)

    for (int j0 = 0; j0 < NPTS; j0 += 32) {
        float dv[32];
#pragma unroll
        for (int u = 0; u < 32; u++) {
            float4 p = s_pts[j0 + u];
            dv[u] = fmaf(qz, p.z, fmaf(qy, p.y, fmaf(qx, p.x, p.w)));
        }
#pragma unroll
        for (int u = 0; u < 32; u++) {
            asm volatile(
                "{ .reg .pred p; setp.lt.f32 p, %1, %2;"
                "  @p st.shared.v2.b32 [%0], {%3, %4};"
                "  @p add.u32 %0, %0, 256; }"
                : "+r"(a)
                : "f"(dv[u]), "f"(worst),
                  "r"(__float_as_int(dv[u])), "r"(j0 + u)
                : "memory");
        }
        int cnt = (int)(a - bufA) >> 8;
        // cap proof: post-check cnt <= 15, +32 -> <= 47 < QDEPTH=48
        if (__any_sync(0xffffffffu, cnt >= 16)) DRAIN(cnt);
    }
    {
        int cnt = (int)(a - bufA) >> 8;
        DRAIN(cnt);
    }
#undef DRAIN

    int* op = g_idx + (b * NPTS + i) * KNN;
#pragma unroll
    for (int k = 0; k < KNN; k++) op[k] = sj[k];

    // ---------------- fused moment accumulation (per-block partials) -----
    const float nqx = -qx, nqy = -qy, nqz = -qz;
    float sd0 = 0.f, sd1 = 0.f, sd2 = 0.f;
    float s00 = 0.f, s01 = 0.f, s02 = 0.f, s11 = 0.f, s12 = 0.f, s22 = 0.f;
#pragma unroll
    for (int k = 0; k < KNN; k++) {
        float4 p = s_pts[sj[k]];
        float d0 = fmaf(-0.5f, p.x, nqx);
        float d1 = fmaf(-0.5f, p.y, nqy);
        float d2 = fmaf(-0.5f, p.z, nqz);
        sd0 += d0; sd1 += d1; sd2 += d2;
        s00 = fmaf(d0, d0, s00); s01 = fmaf(d0, d1, s01); s02 = fmaf(d0, d2, s02);
        s11 = fmaf(d1, d1, s11); s12 = fmaf(d1, d2, s12); s22 = fmaf(d2, d2, s22);
    }

    float v[27];
    v[0] = KNN * qx; v[1] = KNN * qy; v[2] = KNN * qz;
    v[3] = sd0; v[4] = sd1; v[5] = sd2;
    v[6] = KNN * qx * qx; v[7] = KNN * qx * qy; v[8]  = KNN * qx * qz;
    v[9] = KNN * qy * qy; v[10] = KNN * qy * qz; v[11] = KNN * qz * qz;
    v[12] = qx * sd0; v[13] = qx * sd1; v[14] = qx * sd2;
    v[15] = qy * sd0; v[16] = qy * sd1; v[17] = qy * sd2;
    v[18] = qz * sd0; v[19] = qz * sd1; v[20] = qz * sd2;
    v[21] = s00; v[22] = s01; v[23] = s02; v[24] = s11; v[25] = s12; v[26] = s22;

#pragma unroll
    for (int q = 0; q < 27; q++) {
#pragma unroll
        for (int off = 16; off > 0; off >>= 1)
            v[q] += __shfl_down_sync(0xffffffffu, v[q], off);
    }

    if (threadIdx.x < 27) sh[threadIdx.x] = 0.0;
    __syncthreads();
    if ((threadIdx.x & 31) == 0) {
#pragma unroll
        for (int q = 0; q < 27; q++) atomicAdd(&sh[q], (double)v[q]);
    }
    __syncthreads();
    if (threadIdx.x < 27)
        g_bpart[b][blockIdx.x][threadIdx.x] = sh[threadIdx.x];
}

// ---------------------------------------------------------------------------
// Kernel 2: reduce block partials -> per-(b,o) mean/rstd (redundant per
// block, cheap), then conv + tree-max over k + normalize + leaky.
// 64-thread blocks (512 total) -> ~4 blocks/SM co-resident to hide the
// scattered neighbor-gather latency.
// ---------------------------------------------------------------------------
__global__ void __launch_bounds__(64) k_out(const float* __restrict__ x,
                                            const float* __restrict__ W,
                                            float* __restrict__ out) {
    const int b = blockIdx.y;
    const int n = blockIdx.x * 64 + threadIdx.x;

    __shared__ double sG[27];
    __shared__ float sW[OCH * 6];
    __shared__ float sM[OCH];
    __shared__ float sR[OCH];

    if (threadIdx.x < 27) {
        double acc = 0.0;
        for (int blk = 0; blk < KBLK; blk++) acc += g_bpart[b][blk][threadIdx.x];
        sG[threadIdx.x] = acc;
    }
    for (int t = threadIdx.x; t < OCH * 6; t += 64) sW[t] = W[t];
    __syncthreads();

    {
        const int o = threadIdx.x;   // 64 threads == OCH
        double wa0 = sW[o * 6 + 0], wa1 = sW[o * 6 + 1], wa2 = sW[o * 6 + 2];
        double wb0 = sW[o * 6 + 3], wb1 = sW[o * 6 + 4], wb2 = sW[o * 6 + 5];
        const double NK = (double)NPTS * (double)KNN;

        double mean = (wa0 * sG[0] + wa1 * sG[1] + wa2 * sG[2] +
                       wb0 * sG[3] + wb1 * sG[4] + wb2 * sG[5]) / NK;
        double xx = wa0 * wa0 * sG[6] + 2.0 * wa0 * wa1 * sG[7] + 2.0 * wa0 * wa2 * sG[8] +
                    wa1 * wa1 * sG[9] + 2.0 * wa1 * wa2 * sG[10] + wa2 * wa2 * sG[11];
        double xd = wa0 * (wb0 * sG[12] + wb1 * sG[13] + wb2 * sG[14]) +
                    wa1 * (wb0 * sG[15] + wb1 * sG[16] + wb2 * sG[17]) +
                    wa2 * (wb0 * sG[18] + wb1 * sG[19] + wb2 * sG[20]);
        double dd = wb0 * wb0 * sG[21] + 2.0 * wb0 * wb1 * sG[22] + 2.0 * wb0 * wb2 * sG[23] +
                    wb1 * wb1 * sG[24] + 2.0 * wb1 * wb2 * sG[25] + wb2 * wb2 * sG[26];

        double Ey2 = (xx + 2.0 * xd + dd) / NK;
        double var = Ey2 - mean * mean;
        sM[o] = (float)mean;
        sR[o] = (float)(1.0 / sqrt(var + EPS));
    }
    __syncthreads();

    const float* xb = x + b * 3 * NPTS;
    const float xi0 = xb[n], xi1 = xb[NPTS + n], xi2 = xb[2 * NPTS + n];
    const int* ip = g_idx + (b * NPTS + n) * KNN;

    float d0[KNN], d1[KNN], d2[KNN];
#pragma unroll
    for (int k = 0; k < KNN; k++) {
        int j = ip[k];
        d0[k] = xb[j] - xi0;
        d1[k] = xb[NPTS + j] - xi1;
        d2[k] = xb[2 * NPTS + j] - xi2;
    }

    float* ob = out + (size_t)b * OCH * NPTS + n;
    for (int o = 0; o < OCH; o++) {
        float wa0 = sW[o * 6 + 0], wa1 = sW[o * 6 + 1], wa2 = sW[o * 6 + 2];
        float wb0 = sW[o * 6 + 3], wb1 = sW[o * 6 + 4], wb2 = sW[o * 6 + 5];
        float p = wa0 * xi0;
        p = fmaf(wa1, xi1, p);
        p = fmaf(wa2, xi2, p);
        float y[KNN];
#pragma unroll
        for (int k = 0; k < KNN; k++)
            y[k] = fmaf(wb2, d2[k], fmaf(wb1, d1[k], fmaf(wb0, d0[k], p)));
#pragma unroll
        for (int k = 0; k < 10; k++) y[k] = fmaxf(y[k], y[k + 10]);
#pragma unroll
        for (int k = 0; k < 5; k++) y[k] = fmaxf(y[k], y[k + 5]);
        y[0] = fmaxf(y[0], y[2]);
        y[1] = fmaxf(y[1], y[3]);
        float m = fmaxf(fmaxf(y[0], y[1]), y[4]);

        float z = (m - sM[o]) * sR[o];
        ob[(size_t)o * NPTS] = (z >= 0.f) ? z : SLOPE * z;
    }
}

// ---------------------------------------------------------------------------
extern "C" void kernel_launch(void* const* d_in, const int* in_sizes, int n_in,
                              void* d_out, int out_size) {
    const float* x = (const float*)d_in[0];   // [B, C, N]
    const float* W = (const float*)d_in[1];   // [O, 2C]
    float* out = (float*)d_out;               // [B, O, N]

    cudaFuncSetAttribute(k_knn, cudaFuncAttributeMaxDynamicSharedMemorySize,
                         SMEM_TOTAL);

    dim3 gknn(KBLK, B);
    dim3 gout(NPTS / 64, B);

    k_knn<<<gknn, KTHR, SMEM_TOTAL>>>(x);
    k_out<<<gout, 64>>>(x, W, out);
}

// round 15
// speedup vs baseline: 1.0778x; 1.0778x over previous
#include <cuda_runtime.h>
#include <math.h>
#include <stdint.h>

// Problem constants
#define B 4
#define NPTS 8192
#define KNN 20
#define OCH 64
#define EPS 1e-5
#define SLOPE 0.2f
#define INFF __int_as_float(0x7f800000)

// k_knn grid: 37 blocks x 224 threads per batch = 8288 slots (96 masked)
#define KBLK 37
#define KTHR 224
#define KWARPS 7

// dynamic smem: [0,128K) staged points, then 7 per-warp lane queues depth 48
#define PTS_BYTES (NPTS * 16)
#define QDEPTH 48
#define WQ_BYTES (32 * QDEPTH * 8)                  // 12288 per warp
#define SMEM_TOTAL (PTS_BYTES + KWARPS * WQ_BYTES)  // 217088 B

// Device scratch (no allocations allowed)
__device__ int    g_idx[B * NPTS * KNN];
__device__ double g_bpart[B][KBLK][27];   // per-block moment partials (overwritten)

// ---------------------------------------------------------------------------
// Branchless stable insertion into sorted-ascending (d, j) list of 20.
// Upper-bound placement (strict <): ties land AFTER equal entries; candidates
// arrive in ascending j -> jax top_k boundary semantics. Idempotent for +INF.
// ---------------------------------------------------------------------------
__device__ __forceinline__ void insert_dj(float (&sd)[KNN], int (&sj)[KNN],
                                          float vd, int vj) {
    bool c[KNN];
#pragma unroll
    for (int k = 0; k < KNN; k++) c[k] = vd < sd[k];
#pragma unroll
    for (int k = KNN - 1; k >= 1; k--) {
        float td = c[k] ? vd : sd[k];
        int   tj = c[k] ? vj : sj[k];
        sd[k] = c[k - 1] ? sd[k - 1] : td;
        sj[k] = c[k - 1] ? sj[k - 1] : tj;
    }
    sd[0] = c[0] ? vd : sd[0];
    sj[0] = c[0] ? vj : sj[0];
}

// ---------------------------------------------------------------------------
// Kernel 1: flat exact KNN + per-block moment partials (R13 structure).
// Per 32-point group: PHASE 1 pure LDS+math, PHASE 2 predicated PTX queue
// stores. The store asm is volatile but carries NO memory clobber: queue
// order is enforced by the cnt data chain, and the compiler is free to hoist
// the NEXT group's s_pts loads across the stores (cross-group software
// pipelining). A compiler barrier at DRAIN entry orders queue reads after
// the stores (same-thread smem is HW-ordered). One uniform drain-check
// branch per group. Shifted distance d' = d - |q|^2 (set-equivalent).
// ---------------------------------------------------------------------------
__global__ void __launch_bounds__(KTHR) k_knn(const float* __restrict__ x) {
    extern __shared__ char sm[];
    float4* s_pts = (float4*)sm;
    __shared__ double sh[27];

    const int b = blockIdx.y;
    const float* xb = x + b * 3 * NPTS;

    for (int j = threadIdx.x; j < NPTS; j += KTHR) {
        float a0 = xb[j];
        float a1 = xb[NPTS + j];
        float a2 = xb[2 * NPTS + j];
        float sq = fmaf(a0, a0, fmaf(a1, a1, a2 * a2));
        s_pts[j] = make_float4(-2.0f * a0, -2.0f * a1, -2.0f * a2, sq);
    }
    __syncthreads();

    const int tid = threadIdx.x;
    const int iraw = blockIdx.x * KTHR + tid;
    const bool valid = iraw < NPTS;
    const int i = valid ? iraw : (NPTS - 1);
    const float4 ps = s_pts[i];
    const float qx = -0.5f * ps.x, qy = -0.5f * ps.y, qz = -0.5f * ps.z;

    uint32_t sbase;
    asm("{ .reg .u64 t; cvta.to.shared.u64 t, %1; cvt.u32.u64 %0, t; }"
        : "=r"(sbase) : "l"(sm));
    const uint32_t bufA = sbase + (uint32_t)PTS_BYTES +
                          (uint32_t)(tid >> 5) * (uint32_t)WQ_BYTES +
                          (uint32_t)(tid & 31) * 8u;
    const float2* bufP = (const float2*)(sm + PTS_BYTES +
                          (tid >> 5) * WQ_BYTES + (tid & 31) * 8);

    float sd[KNN];
    int   sj[KNN];
#pragma unroll
    for (int k = 0; k < KNN; k++) { sd[k] = INFF; sj[k] = 0; }
    float worst = INFF;
    int   cnt = 0;

#define DRAIN() do {                                                   \
        asm volatile("" ::: "memory");  /* order queue reads after stores */ \
        for (int e = 0; __any_sync(0xffffffffu, e < cnt); e++) {       \
            float2 v = bufP[e * 32];                                   \
            float vd = (e < cnt) ? v.x : INFF;                         \
            insert_dj(sd, sj, vd, __float_as_int(v.y));                \
        }                                                              \
        worst = sd[KNN - 1];                                           \
        cnt = 0;                                                       \
    } while (0)

    for (int j0 = 0; j0 < NPTS; j0 += 32) {
        // PHASE 1: pure loads + math (no clobber anywhere -> loads pipeline
        // across groups)
        float dv[32];
#pragma unroll
        for (int u = 0; u < 32; u++) {
            float4 p = s_pts[j0 + u];
            dv[u] = fmaf(qz, p.z, fmaf(qy, p.y, fmaf(qx, p.x, p.w)));
        }
        // PHASE 2: predicated queue stores; volatile (never deleted) but NO
        // memory clobber. cnt data chain fixes entry order (ascending j).
#pragma unroll
        for (int u = 0; u < 32; u++) {
            bool t = dv[u] < worst;
            uint32_t a = bufA + (uint32_t)cnt * 256u;
            asm volatile(
                "{ .reg .pred p; setp.ne.u32 p, %0, 0;"
                "  @p st.shared.v2.b32 [%1], {%2, %3}; }"
                :: "r"((uint32_t)t), "r"(a), "r"(__float_as_int(dv[u])),
                   "r"(j0 + u));
            cnt += t;
        }
        // cap proof: post-check cnt <= 15, +32 -> <= 47 < QDEPTH=48
        if (__any_sync(0xffffffffu, cnt >= 16)) DRAIN();
    }
    DRAIN();
#undef DRAIN

    if (valid) {
        int* op = g_idx + (b * NPTS + i) * KNN;
#pragma unroll
        for (int k = 0; k < KNN; k++) op[k] = sj[k];
    }

    // ---------------- fused moment accumulation (per-block partials) -----
    const float nqx = -qx, nqy = -qy, nqz = -qz;
    float sd0 = 0.f, sd1 = 0.f, sd2 = 0.f;
    float s00 = 0.f, s01 = 0.f, s02 = 0.f, s11 = 0.f, s12 = 0.f, s22 = 0.f;
#pragma unroll
    for (int k = 0; k < KNN; k++) {
        float4 p = s_pts[sj[k]];
        float d0 = fmaf(-0.5f, p.x, nqx);
        float d1 = fmaf(-0.5f, p.y, nqy);
        float d2 = fmaf(-0.5f, p.z, nqz);
        sd0 += d0; sd1 += d1; sd2 += d2;
        s00 = fmaf(d0, d0, s00); s01 = fmaf(d0, d1, s01); s02 = fmaf(d0, d2, s02);
        s11 = fmaf(d1, d1, s11); s12 = fmaf(d1, d2, s12); s22 = fmaf(d2, d2, s22);
    }

    float v[27];
    v[0] = KNN * qx; v[1] = KNN * qy; v[2] = KNN * qz;
    v[3] = sd0; v[4] = sd1; v[5] = sd2;
    v[6] = KNN * qx * qx; v[7] = KNN * qx * qy; v[8]  = KNN * qx * qz;
    v[9] = KNN * qy * qy; v[10] = KNN * qy * qz; v[11] = KNN * qz * qz;
    v[12] = qx * sd0; v[13] = qx * sd1; v[14] = qx * sd2;
    v[15] = qy * sd0; v[16] = qy * sd1; v[17] = qy * sd2;
    v[18] = qz * sd0; v[19] = qz * sd1; v[20] = qz * sd2;
    v[21] = s00; v[22] = s01; v[23] = s02; v[24] = s11; v[25] = s12; v[26] = s22;

    const float vm = valid ? 1.0f : 0.0f;
#pragma unroll
    for (int q = 0; q < 27; q++) {
        v[q] *= vm;
#pragma unroll
        for (int off = 16; off > 0; off >>= 1)
            v[q] += __shfl_down_sync(0xffffffffu, v[q], off);
    }

    if (threadIdx.x < 27) sh[threadIdx.x] = 0.0;
    __syncthreads();
    if ((threadIdx.x & 31) == 0) {
#pragma unroll
        for (int q = 0; q < 27; q++) atomicAdd(&sh[q], (double)v[q]);
    }
    __syncthreads();
    if (threadIdx.x < 27)
        g_bpart[b][blockIdx.x][threadIdx.x] = sh[threadIdx.x];
}

// ---------------------------------------------------------------------------
// Kernel 2 (R13 form): reduce block partials -> per-(b,o) mean/rstd
// (redundant per block, cheap), then conv + tree-max over k + normalize +
// leaky. 256-thread blocks.
// ---------------------------------------------------------------------------
__global__ void k_out(const float* __restrict__ x, const float* __restrict__ W,
                      float* __restrict__ out) {
    const int b = blockIdx.y;
    const int n = blockIdx.x * blockDim.x + threadIdx.x;

    __shared__ double sG[27];
    __shared__ float sW[OCH * 6];
    __shared__ float sM[OCH];
    __shared__ float sR[OCH];

    if (threadIdx.x < 27) {
        double acc = 0.0;
        for (int blk = 0; blk < KBLK; blk++) acc += g_bpart[b][blk][threadIdx.x];
        sG[threadIdx.x] = acc;
    }
    for (int t = threadIdx.x; t < OCH * 6; t += blockDim.x) sW[t] = W[t];
    __syncthreads();

    if (threadIdx.x < OCH) {
        const int o = threadIdx.x;
        double wa0 = sW[o * 6 + 0], wa1 = sW[o * 6 + 1], wa2 = sW[o * 6 + 2];
        double wb0 = sW[o * 6 + 3], wb1 = sW[o * 6 + 4], wb2 = sW[o * 6 + 5];
        const double NK = (double)NPTS * (double)KNN;

        double mean = (wa0 * sG[0] + wa1 * sG[1] + wa2 * sG[2] +
                       wb0 * sG[3] + wb1 * sG[4] + wb2 * sG[5]) / NK;
        double xx = wa0 * wa0 * sG[6] + 2.0 * wa0 * wa1 * sG[7] + 2.0 * wa0 * wa2 * sG[8] +
                    wa1 * wa1 * sG[9] + 2.0 * wa1 * wa2 * sG[10] + wa2 * wa2 * sG[11];
        double xd = wa0 * (wb0 * sG[12] + wb1 * sG[13] + wb2 * sG[14]) +
                    wa1 * (wb0 * sG[15] + wb1 * sG[16] + wb2 * sG[17]) +
                    wa2 * (wb0 * sG[18] + wb1 * sG[19] + wb2 * sG[20]);
        double dd = wb0 * wb0 * sG[21] + 2.0 * wb0 * wb1 * sG[22] + 2.0 * wb0 * wb2 * sG[23] +
                    wb1 * wb1 * sG[24] + 2.0 * wb1 * wb2 * sG[25] + wb2 * wb2 * sG[26];

        double Ey2 = (xx + 2.0 * xd + dd) / NK;
        double var = Ey2 - mean * mean;
        sM[o] = (float)mean;
        sR[o] = (float)(1.0 / sqrt(var + EPS));
    }
    __syncthreads();

    const float* xb = x + b * 3 * NPTS;
    const float xi0 = xb[n], xi1 = xb[NPTS + n], xi2 = xb[2 * NPTS + n];
    const int* ip = g_idx + (b * NPTS + n) * KNN;

    float d0[KNN], d1[KNN], d2[KNN];
#pragma unroll
    for (int k = 0; k < KNN; k++) {
        int j = ip[k];
        d0[k] = xb[j] - xi0;
        d1[k] = xb[NPTS + j] - xi1;
        d2[k] = xb[2 * NPTS + j] - xi2;
    }

    float* ob = out + (size_t)b * OCH * NPTS + n;
    for (int o = 0; o < OCH; o++) {
        float wa0 = sW[o * 6 + 0], wa1 = sW[o * 6 + 1], wa2 = sW[o * 6 + 2];
        float wb0 = sW[o * 6 + 3], wb1 = sW[o * 6 + 4], wb2 = sW[o * 6 + 5];
        float p = wa0 * xi0;
        p = fmaf(wa1, xi1, p);
        p = fmaf(wa2, xi2, p);
        float y[KNN];
#pragma unroll
        for (int k = 0; k < KNN; k++)
            y[k] = fmaf(wb2, d2[k], fmaf(wb1, d1[k], fmaf(wb0, d0[k], p)));
        // tree max (depth 5) instead of a 20-deep serial chain
#pragma unroll
        for (int k = 0; k < 10; k++) y[k] = fmaxf(y[k], y[k + 10]);
#pragma unroll
        for (int k = 0; k < 5; k++) y[k] = fmaxf(y[k], y[k + 5]);
        y[0] = fmaxf(y[0], y[2]);
        y[1] = fmaxf(y[1], y[3]);
        float m = fmaxf(fmaxf(y[0], y[1]), y[4]);

        float z = (m - sM[o]) * sR[o];
        ob[(size_t)o * NPTS] = (z >= 0.f) ? z : SLOPE * z;
    }
}

// ---------------------------------------------------------------------------
extern "C" void kernel_launch(void* const* d_in, const int* in_sizes, int n_in,
                              void* d_out, int out_size) {
    const float* x = (const float*)d_in[0];   // [B, C, N]
    const float* W = (const float*)d_in[1];   // [O, 2C]
    float* out = (float*)d_out;               // [B, O, N]

    cudaFuncSetAttribute(k_knn, cudaFuncAttributeMaxDynamicSharedMemorySize,
                         SMEM_TOTAL);

    dim3 gknn(KBLK, B);            // 148 blocks total, one per SM
    dim3 gout(NPTS / 256, B);

    k_knn<<<gknn, KTHR, SMEM_TOTAL>>>(x);
    k_out<<<gout, 256>>>(x, W, out);
}

// round 17
// speedup vs baseline: 1.1341x; 1.0522x over previous
#include <cuda_runtime.h>
#include <math.h>
#include <stdint.h>

// Problem constants
#define B 4
#define NPTS 8192
#define KNN 20
#define OCH 64
#define EPS 1e-5
#define SLOPE 0.2f
#define INFF __int_as_float(0x7f800000)

// k_knn grid: 37 blocks x 224 threads per batch = 8288 slots (96 masked)
#define KBLK 37
#define KTHR 224
#define KWARPS 7

// dynamic smem: [0,128K) staged points, then 7 per-warp lane queues depth 48
#define PTS_BYTES (NPTS * 16)
#define QDEPTH 48
#define WQ_BYTES (32 * QDEPTH * 8)                  // 12288 per warp
#define SMEM_TOTAL (PTS_BYTES + KWARPS * WQ_BYTES)  // 217088 B

// Device scratch (no allocations allowed)
__device__ float  g_edge[B * 3 * KNN * NPTS];   // neighbor deltas, coalesced in n (7.9 MB)
__device__ double g_bpart[B][KBLK][27];          // per-block moment partials (overwritten)

// ---------------------------------------------------------------------------
// Branchless stable insertion into sorted-ascending (d, j) list of 20.
// Upper-bound placement (strict <): ties land AFTER equal entries; candidates
// arrive in ascending j -> jax top_k boundary semantics. Idempotent for +INF.
// ---------------------------------------------------------------------------
__device__ __forceinline__ void insert_dj(float (&sd)[KNN], int (&sj)[KNN],
                                          float vd, int vj) {
    bool c[KNN];
#pragma unroll
    for (int k = 0; k < KNN; k++) c[k] = vd < sd[k];
#pragma unroll
    for (int k = KNN - 1; k >= 1; k--) {
        float td = c[k] ? vd : sd[k];
        int   tj = c[k] ? vj : sj[k];
        sd[k] = c[k - 1] ? sd[k - 1] : td;
        sj[k] = c[k - 1] ? sj[k - 1] : tj;
    }
    sd[0] = c[0] ? vd : sd[0];
    sj[0] = c[0] ? vj : sj[0];
}

// ---------------------------------------------------------------------------
// Kernel 1: flat exact KNN (R13's byte-identical hot loop) + per-block
// moment partials + coalesced edge-delta emission. Per 32-point group:
// PHASE 1 pure LDS+math (batched LDS.128), PHASE 2 fused predicated PTX
// (setp.lt + @p st + @p add). One uniform drain-check branch per group.
// Shifted distance d' = d - |q|^2 (monotone per query; index SET unchanged).
// ---------------------------------------------------------------------------
__global__ void __launch_bounds__(KTHR) k_knn(const float* __restrict__ x) {
    extern __shared__ char sm[];
    float4* s_pts = (float4*)sm;
    __shared__ double sh[27];

    const int b = blockIdx.y;
    const float* xb = x + b * 3 * NPTS;

    for (int j = threadIdx.x; j < NPTS; j += KTHR) {
        float a0 = xb[j];
        float a1 = xb[NPTS + j];
        float a2 = xb[2 * NPTS + j];
        float sq = fmaf(a0, a0, fmaf(a1, a1, a2 * a2));
        s_pts[j] = make_float4(-2.0f * a0, -2.0f * a1, -2.0f * a2, sq);
    }
    __syncthreads();

    const int tid = threadIdx.x;
    const int iraw = blockIdx.x * KTHR + tid;
    const bool valid = iraw < NPTS;
    const int i = valid ? iraw : (NPTS - 1);
    const float4 ps = s_pts[i];
    const float qx = -0.5f * ps.x, qy = -0.5f * ps.y, qz = -0.5f * ps.z;

    uint32_t sbase;
    asm("{ .reg .u64 t; cvta.to.shared.u64 t, %1; cvt.u32.u64 %0, t; }"
        : "=r"(sbase) : "l"(sm));
    const uint32_t bufA = sbase + (uint32_t)PTS_BYTES +
                          (uint32_t)(tid >> 5) * (uint32_t)WQ_BYTES +
                          (uint32_t)(tid & 31) * 8u;
    const float2* bufP = (const float2*)(sm + PTS_BYTES +
                          (tid >> 5) * WQ_BYTES + (tid & 31) * 8);

    float sd[KNN];
    int   sj[KNN];
#pragma unroll
    for (int k = 0; k < KNN; k++) { sd[k] = INFF; sj[k] = 0; }
    float worst = INFF;
    int   cnt = 0;

#define DRAIN() do {                                                   \
        for (int e = 0; __any_sync(0xffffffffu, e < cnt); e++) {       \
            float2 v = bufP[e * 32];                                   \
            float vd = (e < cnt) ? v.x : INFF;                         \
            insert_dj(sd, sj, vd, __float_as_int(v.y));                \
        }                                                              \
        worst = sd[KNN - 1];                                           \
        cnt = 0;                                                       \
    } while (0)

    for (int j0 = 0; j0 < NPTS; j0 += 32) {
        float dv[32];
#pragma unroll
        for (int u = 0; u < 32; u++) {
            float4 p = s_pts[j0 + u];
            dv[u] = fmaf(qz, p.z, fmaf(qy, p.y, fmaf(qx, p.x, p.w)));
        }
#pragma unroll
        for (int u = 0; u < 32; u++) {
            uint32_t a = bufA + (uint32_t)cnt * 256u;
            asm volatile(
                "{ .reg .pred p; setp.lt.f32 p, %2, %3;"
                "  @p st.shared.v2.b32 [%1], {%4, %5};"
                "  @p add.u32 %0, %0, 1; }"
                : "+r"(cnt)
                : "r"(a), "f"(dv[u]), "f"(worst),
                  "r"(__float_as_int(dv[u])), "r"(j0 + u)
                : "memory");
        }
        // cap proof: post-check cnt <= 15, +32 -> <= 47 < QDEPTH=48
        if (__any_sync(0xffffffffu, cnt >= 16)) DRAIN();
    }
    DRAIN();
#undef DRAIN

    // ---------------- fused moment accumulation (per-block partials) -----
    const float nqx = -qx, nqy = -qy, nqz = -qz;
    float sd0 = 0.f, sd1 = 0.f, sd2 = 0.f;
    float s00 = 0.f, s01 = 0.f, s02 = 0.f, s11 = 0.f, s12 = 0.f, s22 = 0.f;
#pragma unroll
    for (int k = 0; k < KNN; k++) {
        float4 p = s_pts[sj[k]];
        float d0 = fmaf(-0.5f, p.x, nqx);
        float d1 = fmaf(-0.5f, p.y, nqy);
        float d2 = fmaf(-0.5f, p.z, nqz);
        sd0 += d0; sd1 += d1; sd2 += d2;
        s00 = fmaf(d0, d0, s00); s01 = fmaf(d0, d1, s01); s02 = fmaf(d0, d2, s02);
        s11 = fmaf(d1, d1, s11); s12 = fmaf(d1, d2, s12); s22 = fmaf(d2, d2, s22);
    }

    // ---------------- emit coalesced edge deltas (replaces g_idx) --------
    // fmaf(-0.5, p.c, nq.c) is single-rounded x_j - x_i: bit-identical to
    // the subtraction k_out used to compute from gathered coordinates.
    if (valid) {
        float* eb = g_edge + (size_t)b * 3 * KNN * NPTS + i;
#pragma unroll
        for (int k = 0; k < KNN; k++) {
            float4 p = s_pts[sj[k]];
            eb[(0 * KNN + k) * NPTS] = fmaf(-0.5f, p.x, nqx);
            eb[(1 * KNN + k) * NPTS] = fmaf(-0.5f, p.y, nqy);
            eb[(2 * KNN + k) * NPTS] = fmaf(-0.5f, p.z, nqz);
        }
    }

    float v[27];
    v[0] = KNN * qx; v[1] = KNN * qy; v[2] = KNN * qz;
    v[3] = sd0; v[4] = sd1; v[5] = sd2;
    v[6] = KNN * qx * qx; v[7] = KNN * qx * qy; v[8]  = KNN * qx * qz;
    v[9] = KNN * qy * qy; v[10] = KNN * qy * qz; v[11] = KNN * qz * qz;
    v[12] = qx * sd0; v[13] = qx * sd1; v[14] = qx * sd2;
    v[15] = qy * sd0; v[16] = qy * sd1; v[17] = qy * sd2;
    v[18] = qz * sd0; v[19] = qz * sd1; v[20] = qz * sd2;
    v[21] = s00; v[22] = s01; v[23] = s02; v[24] = s11; v[25] = s12; v[26] = s22;

    const float vm = valid ? 1.0f : 0.0f;
#pragma unroll
    for (int q = 0; q < 27; q++) {
        v[q] *= vm;
#pragma unroll
        for (int off = 16; off > 0; off >>= 1)
            v[q] += __shfl_down_sync(0xffffffffu, v[q], off);
    }

    if (threadIdx.x < 27) sh[threadIdx.x] = 0.0;
    __syncthreads();
    if ((threadIdx.x & 31) == 0) {
#pragma unroll
        for (int q = 0; q < 27; q++) atomicAdd(&sh[q], (double)v[q]);
    }
    __syncthreads();
    if (threadIdx.x < 27)
        g_bpart[b][blockIdx.x][threadIdx.x] = sh[threadIdx.x];
}

// ---------------------------------------------------------------------------
// Kernel 2: reduce block partials -> per-(b,o) mean/rstd (redundant per
// block, cheap), then conv + tree-max over k + normalize + leaky.
// Edge deltas come in COALESCED from g_edge (no index loads, no scatter).
// Weights padded to stride 8 in a 16B-ALIGNED smem array -> LDS.128+LDS.64.
// ---------------------------------------------------------------------------
__global__ void k_out(const float* __restrict__ x, const float* __restrict__ W,
                      float* __restrict__ out) {
    const int b = blockIdx.y;
    const int n = blockIdx.x * blockDim.x + threadIdx.x;

    __shared__ double sG[27];
    __shared__ __align__(16) float sW8[OCH * 8];   // 16B alignment for LDS.128
    __shared__ float sM[OCH];
    __shared__ float sR[OCH];

    if (threadIdx.x < 27) {
        double acc = 0.0;
        for (int blk = 0; blk < KBLK; blk++) acc += g_bpart[b][blk][threadIdx.x];
        sG[threadIdx.x] = acc;
    }
    if (threadIdx.x < OCH) {
        const int o = threadIdx.x;
#pragma unroll
        for (int c = 0; c < 6; c++) sW8[o * 8 + c] = W[o * 6 + c];
        sW8[o * 8 + 6] = 0.f; sW8[o * 8 + 7] = 0.f;
    }
    __syncthreads();

    if (threadIdx.x < OCH) {
        const int o = threadIdx.x;
        double wa0 = sW8[o * 8 + 0], wa1 = sW8[o * 8 + 1], wa2 = sW8[o * 8 + 2];
        double wb0 = sW8[o * 8 + 3], wb1 = sW8[o * 8 + 4], wb2 = sW8[o * 8 + 5];
        const double NK = (double)NPTS * (double)KNN;

        double mean = (wa0 * sG[0] + wa1 * sG[1] + wa2 * sG[2] +
                       wb0 * sG[3] + wb1 * sG[4] + wb2 * sG[5]) / NK;
        double xx = wa0 * wa0 * sG[6] + 2.0 * wa0 * wa1 * sG[7] + 2.0 * wa0 * wa2 * sG[8] +
                    wa1 * wa1 * sG[9] + 2.0 * wa1 * wa2 * sG[10] + wa2 * wa2 * sG[11];
        double xd = wa0 * (wb0 * sG[12] + wb1 * sG[13] + wb2 * sG[14]) +
                    wa1 * (wb0 * sG[15] + wb1 * sG[16] + wb2 * sG[17]) +
                    wa2 * (wb0 * sG[18] + wb1 * sG[19] + wb2 * sG[20]);
        double dd = wb0 * wb0 * sG[21] + 2.0 * wb0 * wb1 * sG[22] + 2.0 * wb0 * wb2 * sG[23] +
                    wb1 * wb1 * sG[24] + 2.0 * wb1 * wb2 * sG[25] + wb2 * wb2 * sG[26];

        double Ey2 = (xx + 2.0 * xd + dd) / NK;
        double var = Ey2 - mean * mean;
        sM[o] = (float)mean;
        sR[o] = (float)(1.0 / sqrt(var + EPS));
    }
    __syncthreads();

    const float* xb = x + b * 3 * NPTS;
    const float xi0 = xb[n], xi1 = xb[NPTS + n], xi2 = xb[2 * NPTS + n];

    // coalesced edge-delta loads (60 independent LDG, high MLP)
    const float* eb = g_edge + (size_t)b * 3 * KNN * NPTS + n;
    float d0[KNN], d1[KNN], d2[KNN];
#pragma unroll
    for (int k = 0; k < KNN; k++) {
        d0[k] = eb[(0 * KNN + k) * NPTS];
        d1[k] = eb[(1 * KNN + k) * NPTS];
        d2[k] = eb[(2 * KNN + k) * NPTS];
    }

    float* ob = out + (size_t)b * OCH * NPTS + n;
    for (int o = 0; o < OCH; o++) {
        float4 wA = *(const float4*)&sW8[o * 8];
        float2 wB = *(const float2*)&sW8[o * 8 + 4];
        float wa0 = wA.x, wa1 = wA.y, wa2 = wA.z;
        float wb0 = wA.w, wb1 = wB.x, wb2 = wB.y;
        float p = wa0 * xi0;
        p = fmaf(wa1, xi1, p);
        p = fmaf(wa2, xi2, p);
        float y[KNN];
#pragma unroll
        for (int k = 0; k < KNN; k++)
            y[k] = fmaf(wb2, d2[k], fmaf(wb1, d1[k], fmaf(wb0, d0[k], p)));
        // tree max (depth 5)
#pragma unroll
        for (int k = 0; k < 10; k++) y[k] = fmaxf(y[k], y[k + 10]);
#pragma unroll
        for (int k = 0; k < 5; k++) y[k] = fmaxf(y[k], y[k + 5]);
        y[0] = fmaxf(y[0], y[2]);
        y[1] = fmaxf(y[1], y[3]);
        float m = fmaxf(fmaxf(y[0], y[1]), y[4]);

        float z = (m - sM[o]) * sR[o];
        ob[(size_t)o * NPTS] = (z >= 0.f) ? z : SLOPE * z;
    }
}

// ---------------------------------------------------------------------------
extern "C" void kernel_launch(void* const* d_in, const int* in_sizes, int n_in,
                              void* d_out, int out_size) {
    const float* x = (const float*)d_in[0];   // [B, C, N]
    const float* W = (const float*)d_in[1];   // [O, 2C]
    float* out = (float*)d_out;               // [B, O, N]

    cudaFuncSetAttribute(k_knn, cudaFuncAttributeMaxDynamicSharedMemorySize,
                         SMEM_TOTAL);

    dim3 gknn(KBLK, B);            // 148 blocks total, one per SM
    dim3 gout(NPTS / 256, B);

    k_knn<<<gknn, KTHR, SMEM_TOTAL>>>(x);
    k_out<<<gout, 256>>>(x, W, out);
}